// round 6
// baseline (speedup 1.0000x reference)
#include <cuda_runtime.h>
#include <cuda_bf16.h>
#include <cuda_fp16.h>
#include <cstdint>

#define MAX_N 100000
#define MAX_E 1600000
#define D 128
#define NB_MAX 128

// Scratch (device globals -- no allocation allowed)
__device__ __half g_hh[(size_t)MAX_N * D];     // 25.6 MB fp16 h
__device__ float g_si[MAX_N];
__device__ float g_sj[MAX_N];
__device__ int   g_cnt[MAX_N];                 // hist, then countdown cursor
__device__ int   g_offp[MAX_N];                // block-local exclusive prefix
__device__ int   g_bsum[NB_MAX];
__device__ int   g_bpre[NB_MAX];
__device__ uint2 g_de[MAX_E + MAX_N];          // packed (dst, exp(score))

__device__ __forceinline__ unsigned h2_to_u32(__half2 h) {
    unsigned u; *reinterpret_cast<__half2*>(&u) = h; return u;
}
__device__ __forceinline__ __half2 u32_to_h2(unsigned u) {
    return *reinterpret_cast<__half2*>(&u);
}

#define LDSM4(r0, r1, r2, r3, addr)                                        \
    asm volatile("ldmatrix.sync.aligned.m8n8.x4.shared.b16 "               \
                 "{%0,%1,%2,%3}, [%4];"                                    \
                 : "=r"(r0), "=r"(r1), "=r"(r2), "=r"(r3) : "r"(addr))

// ---------------------------------------------------------------------------
__global__ void init_kernel(int n) {
    int i = blockIdx.x * blockDim.x + threadIdx.x;
    if (i < n) g_cnt[i] = 1;                   // self loop
}

// ---------------------------------------------------------------------------
// Tensor-core GEMM: h = x @ W^T + b via mma.sync m16n8k16 + ldmatrix.
// Block tile 128x128, K chunked 2x64. 8 warps: 4 in M x 2 in N.
// ---------------------------------------------------------------------------
#define KC 64
#define XPITCH 72              // smem row pitch in halves (64 + 8 pad)
#define HPITCH 136             // epilogue pitch (128 + 8 pad)

__global__ __launch_bounds__(256, 2)
void gemm_kernel(const float* __restrict__ x, const float* __restrict__ W,
                 const float* __restrict__ b, const float* __restrict__ Watt,
                 int n) {
    __shared__ __align__(16) char smem_raw[2 * 128 * XPITCH * 2]; // 36864 B
    __half (*xs)[XPITCH] = (__half(*)[XPITCH])smem_raw;
    __half (*ws)[XPITCH] = (__half(*)[XPITCH])(smem_raw + 128 * XPITCH * 2);
    __half (*hs)[HPITCH] = (__half(*)[HPITCH])smem_raw;   // epilogue reuse

    int tid = threadIdx.x;
    int wid = tid >> 5;
    int lane = tid & 31;
    int gid = lane >> 2;
    int tig = lane & 3;
    int wm = wid & 3;
    int wn = wid >> 2;
    int row0 = blockIdx.x * 128;

    // ldmatrix source addresses (constant across chunks)
    int lrow = lane & 7, lsel = lane >> 3;
    int aro = (lsel & 1) * 8, ako = (lsel >> 1) * 8;   // A quadrants
    int bno = (lsel >> 1) * 8, bko = (lsel & 1) * 8;   // B quadrants
    unsigned a_addr[2], b_addr[4];
#pragma unroll
    for (int mi = 0; mi < 2; mi++)
        a_addr[mi] = (unsigned)__cvta_generic_to_shared(
            &xs[wm * 32 + mi * 16 + aro + lrow][ako]);
#pragma unroll
    for (int nj = 0; nj < 4; nj++)
        b_addr[nj] = (unsigned)__cvta_generic_to_shared(
            &ws[wn * 64 + nj * 16 + bno + lrow][bko]);

    float c[2][8][4];
#pragma unroll
    for (int mi = 0; mi < 2; mi++)
#pragma unroll
        for (int ni = 0; ni < 8; ni++)
#pragma unroll
            for (int r = 0; r < 4; r++) c[mi][ni][r] = 0.f;

#pragma unroll
    for (int kk = 0; kk < D; kk += KC) {
#pragma unroll
        for (int r = 0; r < 8; r++) {
            int idx = tid + r * 256;
            int row = idx >> 4;
            int c4 = (idx & 15) * 4;
            float4 v = make_float4(0.f, 0.f, 0.f, 0.f);
            int gr = row0 + row;
            if (gr < n) v = *(const float4*)&x[(size_t)gr * D + kk + c4];
            unsigned p0 = h2_to_u32(__floats2half2_rn(v.x, v.y));
            unsigned p1 = h2_to_u32(__floats2half2_rn(v.z, v.w));
            *(uint2*)&xs[row][c4] = make_uint2(p0, p1);
        }
#pragma unroll
        for (int r = 0; r < 8; r++) {
            int idx = tid + r * 256;
            int cc = idx >> 4;
            int c4 = (idx & 15) * 4;
            float4 v = *(const float4*)&W[(size_t)cc * D + kk + c4];
            unsigned p0 = h2_to_u32(__floats2half2_rn(v.x, v.y));
            unsigned p1 = h2_to_u32(__floats2half2_rn(v.z, v.w));
            *(uint2*)&ws[cc][c4] = make_uint2(p0, p1);
        }
        __syncthreads();

#pragma unroll
        for (int ks = 0; ks < KC / 16; ks++) {
            unsigned a[2][4];
#pragma unroll
            for (int mi = 0; mi < 2; mi++)
                LDSM4(a[mi][0], a[mi][1], a[mi][2], a[mi][3],
                      a_addr[mi] + ks * 32);
#pragma unroll
            for (int nj = 0; nj < 4; nj++) {
                unsigned bf[4];
                LDSM4(bf[0], bf[1], bf[2], bf[3], b_addr[nj] + ks * 32);
#pragma unroll
                for (int mi = 0; mi < 2; mi++) {
                    asm volatile(
                        "mma.sync.aligned.m16n8k16.row.col.f32.f16.f16.f32 "
                        "{%0,%1,%2,%3}, {%4,%5,%6,%7}, {%8,%9}, {%0,%1,%2,%3};"
                        : "+f"(c[mi][2*nj][0]), "+f"(c[mi][2*nj][1]),
                          "+f"(c[mi][2*nj][2]), "+f"(c[mi][2*nj][3])
                        : "r"(a[mi][0]), "r"(a[mi][1]), "r"(a[mi][2]), "r"(a[mi][3]),
                          "r"(bf[0]), "r"(bf[1]));
                    asm volatile(
                        "mma.sync.aligned.m16n8k16.row.col.f32.f16.f16.f32 "
                        "{%0,%1,%2,%3}, {%4,%5,%6,%7}, {%8,%9}, {%0,%1,%2,%3};"
                        : "+f"(c[mi][2*nj+1][0]), "+f"(c[mi][2*nj+1][1]),
                          "+f"(c[mi][2*nj+1][2]), "+f"(c[mi][2*nj+1][3])
                        : "r"(a[mi][0]), "r"(a[mi][1]), "r"(a[mi][2]), "r"(a[mi][3]),
                          "r"(bf[2]), "r"(bf[3]));
                }
            }
        }
        __syncthreads();
    }

    // epilogue pass 1: +bias, fp16, stage in smem
#pragma unroll
    for (int mi = 0; mi < 2; mi++) {
#pragma unroll
        for (int ni = 0; ni < 8; ni++) {
            int rr = wm * 32 + mi * 16 + gid;
            int col = wn * 64 + ni * 8 + tig * 2;
            float bx = __ldg(&b[col]);
            float by = __ldg(&b[col + 1]);
            *(unsigned*)&hs[rr][col] =
                h2_to_u32(__floats2half2_rn(c[mi][ni][0] + bx, c[mi][ni][1] + by));
            *(unsigned*)&hs[rr + 8][col] =
                h2_to_u32(__floats2half2_rn(c[mi][ni][2] + bx, c[mi][ni][3] + by));
        }
    }
    __syncthreads();

    // epilogue pass 2: coalesced store + fused s_i/s_j
    int tx = tid & 15;
    int tyr = tid >> 4;
    float ai_r[8], aj_r[8];
#pragma unroll
    for (int j = 0; j < 8; j++) {
        ai_r[j] = __ldg(&Watt[tx * 8 + j]);
        aj_r[j] = __ldg(&Watt[D + tx * 8 + j]);
    }
#pragma unroll
    for (int it = 0; it < 8; it++) {
        int row = it * 16 + tyr;
        int gr = row0 + row;
        uint4 v = *(const uint4*)&hs[row][tx * 8];
        float2 f0 = __half22float2(u32_to_h2(v.x));
        float2 f1 = __half22float2(u32_to_h2(v.y));
        float2 f2 = __half22float2(u32_to_h2(v.z));
        float2 f3 = __half22float2(u32_to_h2(v.w));
        float psi = f0.x*ai_r[0] + f0.y*ai_r[1] + f1.x*ai_r[2] + f1.y*ai_r[3]
                  + f2.x*ai_r[4] + f2.y*ai_r[5] + f3.x*ai_r[6] + f3.y*ai_r[7];
        float psj = f0.x*aj_r[0] + f0.y*aj_r[1] + f1.x*aj_r[2] + f1.y*aj_r[3]
                  + f2.x*aj_r[4] + f2.y*aj_r[5] + f3.x*aj_r[6] + f3.y*aj_r[7];
#pragma unroll
        for (int o = 8; o; o >>= 1) {
            psi += __shfl_down_sync(0xffffffffu, psi, o, 16);
            psj += __shfl_down_sync(0xffffffffu, psj, o, 16);
        }
        if (gr < n) {
            *(uint4*)&g_hh[(size_t)gr * D + tx * 8] = v;
            if (tx == 0) { g_si[gr] = psi; g_sj[gr] = psj; }
        }
    }
}

// ---------------------------------------------------------------------------
__global__ void hist_kernel(const int* __restrict__ ei, int E) {
    int t = blockIdx.x * blockDim.x + threadIdx.x;
    if (t < E) atomicAdd(&g_cnt[ei[t]], 1);
}

// ---------------------------------------------------------------------------
__global__ void scan1_kernel(int n) {
    __shared__ int sh[1024];
    int i = blockIdx.x * 1024 + threadIdx.x;
    int v = (i < n) ? g_cnt[i] : 0;
    sh[threadIdx.x] = v;
    __syncthreads();
    for (int off = 1; off < 1024; off <<= 1) {
        int t = (threadIdx.x >= off) ? sh[threadIdx.x - off] : 0;
        __syncthreads();
        sh[threadIdx.x] += t;
        __syncthreads();
    }
    if (i < n) g_offp[i] = sh[threadIdx.x] - v;
    if (threadIdx.x == 1023) g_bsum[blockIdx.x] = sh[1023];
}

__global__ void scan2_kernel(int nb) {
    __shared__ int sh[NB_MAX];
    int t = threadIdx.x;
    int v = (t < nb) ? g_bsum[t] : 0;
    sh[t] = v;
    __syncthreads();
    for (int off = 1; off < NB_MAX; off <<= 1) {
        int u = (t >= off) ? sh[t - off] : 0;
        __syncthreads();
        sh[t] += u;
        __syncthreads();
    }
    if (t < nb) g_bpre[t] = sh[t] - v;
}

// ---------------------------------------------------------------------------
// scatter: score + exp + countdown bucket placement
// pos = segment_base + (remaining - 1); g_cnt counts down to 0.
// ---------------------------------------------------------------------------
__global__ void scatter_kernel(const int* __restrict__ ei,
                               const float* __restrict__ batt, int E, int n) {
    int t = blockIdx.x * blockDim.x + threadIdx.x;
    if (t >= E + n) return;
    int src, dst;
    if (t < E) { src = ei[t]; dst = ei[E + t]; }
    else       { src = t - E; dst = src; }
    float sc = g_si[src] + g_sj[dst] + batt[0];
    sc = (sc >= 0.f) ? sc : 0.01f * sc;
    float e = expf(sc);
    int old = atomicAdd(&g_cnt[src], -1);
    int pos = g_offp[src] + g_bpre[src >> 10] + old - 1;
    g_de[pos] = make_uint2((unsigned)dst, __float_as_uint(e));
}

// ---------------------------------------------------------------------------
// aggregation: warp per src node, fp16 gather, fp32 accumulate,
// fused normalize + ELU, coalesced write.
// ---------------------------------------------------------------------------
__global__ __launch_bounds__(256)
void aggregate_kernel(float* __restrict__ out, int n, int total) {
    int w = (blockIdx.x * blockDim.x + threadIdx.x) >> 5;
    int lane = threadIdx.x & 31;
    if (w >= n) return;
    int s = g_offp[w] + g_bpre[w >> 10];
    int e = (w + 1 < n) ? (g_offp[w + 1] + g_bpre[(w + 1) >> 10]) : total;

    float4 acc = make_float4(0.f, 0.f, 0.f, 0.f);
    float den = 0.f;

    int k = s;
    for (; k + 3 < e; k += 4) {
        uint2 de0 = g_de[k],     de1 = g_de[k + 1];
        uint2 de2 = g_de[k + 2], de3 = g_de[k + 3];
        uint2 r0 = *(const uint2*)&g_hh[(size_t)de0.x * D + lane * 4];
        uint2 r1 = *(const uint2*)&g_hh[(size_t)de1.x * D + lane * 4];
        uint2 r2 = *(const uint2*)&g_hh[(size_t)de2.x * D + lane * 4];
        uint2 r3 = *(const uint2*)&g_hh[(size_t)de3.x * D + lane * 4];
        float e0 = __uint_as_float(de0.y), e1 = __uint_as_float(de1.y);
        float e2 = __uint_as_float(de2.y), e3 = __uint_as_float(de3.y);
        float2 a0 = __half22float2(u32_to_h2(r0.x));
        float2 a1 = __half22float2(u32_to_h2(r0.y));
        acc.x += e0 * a0.x; acc.y += e0 * a0.y; acc.z += e0 * a1.x; acc.w += e0 * a1.y;
        a0 = __half22float2(u32_to_h2(r1.x));
        a1 = __half22float2(u32_to_h2(r1.y));
        acc.x += e1 * a0.x; acc.y += e1 * a0.y; acc.z += e1 * a1.x; acc.w += e1 * a1.y;
        a0 = __half22float2(u32_to_h2(r2.x));
        a1 = __half22float2(u32_to_h2(r2.y));
        acc.x += e2 * a0.x; acc.y += e2 * a0.y; acc.z += e2 * a1.x; acc.w += e2 * a1.y;
        a0 = __half22float2(u32_to_h2(r3.x));
        a1 = __half22float2(u32_to_h2(r3.y));
        acc.x += e3 * a0.x; acc.y += e3 * a0.y; acc.z += e3 * a1.x; acc.w += e3 * a1.y;
        den += (e0 + e1) + (e2 + e3);
    }
    for (; k < e; k++) {
        uint2 de0 = g_de[k];
        uint2 r0 = *(const uint2*)&g_hh[(size_t)de0.x * D + lane * 4];
        float e0 = __uint_as_float(de0.y);
        float2 a0 = __half22float2(u32_to_h2(r0.x));
        float2 a1 = __half22float2(u32_to_h2(r0.y));
        acc.x += e0 * a0.x; acc.y += e0 * a0.y; acc.z += e0 * a1.x; acc.w += e0 * a1.y;
        den += e0;
    }

    float inv = 1.f / den;
    float4 o;
    o.x = acc.x * inv; o.y = acc.y * inv; o.z = acc.z * inv; o.w = acc.w * inv;
    o.x = (o.x > 0.f) ? o.x : expm1f(o.x);
    o.y = (o.y > 0.f) ? o.y : expm1f(o.y);
    o.z = (o.z > 0.f) ? o.z : expm1f(o.z);
    o.w = (o.w > 0.f) ? o.w : expm1f(o.w);
    *(float4*)&out[(size_t)w * D + lane * 4] = o;
}

// ---------------------------------------------------------------------------
extern "C" void kernel_launch(void* const* d_in, const int* in_sizes, int n_in,
                              void* d_out, int out_size) {
    const float* x    = (const float*)d_in[0];
    const int*   ei   = (const int*)  d_in[1];
    const float* W    = (const float*)d_in[2];
    const float* b    = (const float*)d_in[3];
    const float* Watt = (const float*)d_in[4];
    const float* batt = (const float*)d_in[5];
    float* out = (float*)d_out;

    int n = in_sizes[0] / D;
    int E = in_sizes[1] / 2;
    int total = E + n;
    int nb = (n + 1023) / 1024;

    init_kernel<<<(n + 255) / 256, 256>>>(n);
    gemm_kernel<<<(n + 127) / 128, 256>>>(x, W, b, Watt, n);
    hist_kernel<<<(E + 255) / 256, 256>>>(ei, E);
    scan1_kernel<<<nb, 1024>>>(n);
    scan2_kernel<<<1, NB_MAX>>>(nb);
    scatter_kernel<<<(total + 255) / 256, 256>>>(ei, batt, E, n);
    aggregate_kernel<<<((long long)n * 32 + 255) / 256, 256>>>(out, n, total);
}

// round 7
// speedup vs baseline: 1.0551x; 1.0551x over previous
#include <cuda_runtime.h>
#include <cuda_bf16.h>
#include <cuda_fp16.h>
#include <cstdint>

#define MAX_N 100000
#define MAX_E 1600000
#define D 128
#define NB_MAX 128

// Scratch (device globals -- no allocation allowed)
__device__ __half g_hh[(size_t)MAX_N * D];     // 25.6 MB fp16 h
__device__ float g_si[MAX_N];
__device__ float g_sj[MAX_N];
__device__ int   g_cnt[MAX_N];                 // edge hist; countdown returns it to 0
__device__ int   g_offp[MAX_N];                // block-local exclusive prefix
__device__ int   g_bsum[NB_MAX];
__device__ int   g_bpre[NB_MAX];
__device__ uint2 g_de[MAX_E + MAX_N];          // packed (dst, exp(score))

__device__ __forceinline__ unsigned h2_to_u32(__half2 h) {
    unsigned u; *reinterpret_cast<__half2*>(&u) = h; return u;
}
__device__ __forceinline__ __half2 u32_to_h2(unsigned u) {
    return *reinterpret_cast<__half2*>(&u);
}

// ---------------------------------------------------------------------------
// Tensor-core GEMM: h = x @ W^T + b via mma.sync m16n8k16 f16f16f32.
// Block tile 128x128, K chunked 2x64. 8 warps: 4 in M x 2 in N.
// (round-5 proven mainloop: scalar LDS fragment loads)
// ---------------------------------------------------------------------------
#define KC 64
#define XPITCH 72              // smem row pitch in halves (64 + 8 pad)
#define HPITCH 136             // epilogue pitch (128 + 8 pad)

__global__ __launch_bounds__(256, 2)
void gemm_kernel(const float* __restrict__ x, const float* __restrict__ W,
                 const float* __restrict__ b, const float* __restrict__ Watt,
                 int n) {
    __shared__ __align__(16) char smem_raw[2 * 128 * XPITCH * 2]; // 36864 B
    __half (*xs)[XPITCH] = (__half(*)[XPITCH])smem_raw;
    __half (*ws)[XPITCH] = (__half(*)[XPITCH])(smem_raw + 128 * XPITCH * 2);
    __half (*hs)[HPITCH] = (__half(*)[HPITCH])smem_raw;   // epilogue reuse

    int tid = threadIdx.x;
    int wid = tid >> 5;
    int lane = tid & 31;
    int gid = lane >> 2;
    int tig = lane & 3;
    int wm = wid & 3;
    int wn = wid >> 2;
    int row0 = blockIdx.x * 128;

    float c[2][8][4];
#pragma unroll
    for (int mi = 0; mi < 2; mi++)
#pragma unroll
        for (int ni = 0; ni < 8; ni++)
#pragma unroll
            for (int r = 0; r < 4; r++) c[mi][ni][r] = 0.f;

#pragma unroll
    for (int kk = 0; kk < D; kk += KC) {
#pragma unroll
        for (int r = 0; r < 8; r++) {
            int idx = tid + r * 256;
            int row = idx >> 4;
            int c4 = (idx & 15) * 4;
            float4 v = make_float4(0.f, 0.f, 0.f, 0.f);
            int gr = row0 + row;
            if (gr < n) v = *(const float4*)&x[(size_t)gr * D + kk + c4];
            unsigned p0 = h2_to_u32(__floats2half2_rn(v.x, v.y));
            unsigned p1 = h2_to_u32(__floats2half2_rn(v.z, v.w));
            *(uint2*)&xs[row][c4] = make_uint2(p0, p1);
        }
#pragma unroll
        for (int r = 0; r < 8; r++) {
            int idx = tid + r * 256;
            int cc = idx >> 4;
            int c4 = (idx & 15) * 4;
            float4 v = *(const float4*)&W[(size_t)cc * D + kk + c4];
            unsigned p0 = h2_to_u32(__floats2half2_rn(v.x, v.y));
            unsigned p1 = h2_to_u32(__floats2half2_rn(v.z, v.w));
            *(uint2*)&ws[cc][c4] = make_uint2(p0, p1);
        }
        __syncthreads();

#pragma unroll
        for (int ks = 0; ks < KC / 16; ks++) {
            int kb = ks * 16 + tig * 2;
            unsigned a[2][4];
#pragma unroll
            for (int mi = 0; mi < 2; mi++) {
                int ra = wm * 32 + mi * 16 + gid;
                a[mi][0] = *(const unsigned*)&xs[ra][kb];
                a[mi][1] = *(const unsigned*)&xs[ra + 8][kb];
                a[mi][2] = *(const unsigned*)&xs[ra][kb + 8];
                a[mi][3] = *(const unsigned*)&xs[ra + 8][kb + 8];
            }
#pragma unroll
            for (int ni = 0; ni < 8; ni++) {
                int cb = wn * 64 + ni * 8 + gid;
                unsigned b0 = *(const unsigned*)&ws[cb][kb];
                unsigned b1 = *(const unsigned*)&ws[cb][kb + 8];
#pragma unroll
                for (int mi = 0; mi < 2; mi++) {
                    asm volatile(
                        "mma.sync.aligned.m16n8k16.row.col.f32.f16.f16.f32 "
                        "{%0,%1,%2,%3}, {%4,%5,%6,%7}, {%8,%9}, {%0,%1,%2,%3};"
                        : "+f"(c[mi][ni][0]), "+f"(c[mi][ni][1]),
                          "+f"(c[mi][ni][2]), "+f"(c[mi][ni][3])
                        : "r"(a[mi][0]), "r"(a[mi][1]), "r"(a[mi][2]), "r"(a[mi][3]),
                          "r"(b0), "r"(b1));
                }
            }
        }
        __syncthreads();
    }

    // epilogue pass 1: +bias, fp16, stage in smem
#pragma unroll
    for (int mi = 0; mi < 2; mi++) {
#pragma unroll
        for (int ni = 0; ni < 8; ni++) {
            int rr = wm * 32 + mi * 16 + gid;
            int col = wn * 64 + ni * 8 + tig * 2;
            float bx = __ldg(&b[col]);
            float by = __ldg(&b[col + 1]);
            *(unsigned*)&hs[rr][col] =
                h2_to_u32(__floats2half2_rn(c[mi][ni][0] + bx, c[mi][ni][1] + by));
            *(unsigned*)&hs[rr + 8][col] =
                h2_to_u32(__floats2half2_rn(c[mi][ni][2] + bx, c[mi][ni][3] + by));
        }
    }
    __syncthreads();

    // epilogue pass 2: coalesced store + fused s_i/s_j
    int tx = tid & 15;
    int tyr = tid >> 4;
    float ai_r[8], aj_r[8];
#pragma unroll
    for (int j = 0; j < 8; j++) {
        ai_r[j] = __ldg(&Watt[tx * 8 + j]);
        aj_r[j] = __ldg(&Watt[D + tx * 8 + j]);
    }
#pragma unroll
    for (int it = 0; it < 8; it++) {
        int row = it * 16 + tyr;
        int gr = row0 + row;
        uint4 v = *(const uint4*)&hs[row][tx * 8];
        float2 f0 = __half22float2(u32_to_h2(v.x));
        float2 f1 = __half22float2(u32_to_h2(v.y));
        float2 f2 = __half22float2(u32_to_h2(v.z));
        float2 f3 = __half22float2(u32_to_h2(v.w));
        float psi = f0.x*ai_r[0] + f0.y*ai_r[1] + f1.x*ai_r[2] + f1.y*ai_r[3]
                  + f2.x*ai_r[4] + f2.y*ai_r[5] + f3.x*ai_r[6] + f3.y*ai_r[7];
        float psj = f0.x*aj_r[0] + f0.y*aj_r[1] + f1.x*aj_r[2] + f1.y*aj_r[3]
                  + f2.x*aj_r[4] + f2.y*aj_r[5] + f3.x*aj_r[6] + f3.y*aj_r[7];
#pragma unroll
        for (int o = 8; o; o >>= 1) {
            psi += __shfl_down_sync(0xffffffffu, psi, o, 16);
            psj += __shfl_down_sync(0xffffffffu, psj, o, 16);
        }
        if (gr < n) {
            *(uint4*)&g_hh[(size_t)gr * D + tx * 8] = v;
            if (tx == 0) { g_si[gr] = psi; g_sj[gr] = psj; }
        }
    }
}

// ---------------------------------------------------------------------------
__global__ void hist_kernel(const int* __restrict__ ei, int E) {
    int t = blockIdx.x * blockDim.x + threadIdx.x;
    if (t < E) atomicAdd(&g_cnt[ei[t]], 1);
}

// ---------------------------------------------------------------------------
// scan1 reads cnt[i]+1 (implicit self-loop); g_cnt itself stays the raw
// edge histogram, and scatter's countdown returns it to 0 for the next replay.
// ---------------------------------------------------------------------------
__global__ void scan1_kernel(int n) {
    __shared__ int sh[1024];
    int i = blockIdx.x * 1024 + threadIdx.x;
    int v = (i < n) ? (g_cnt[i] + 1) : 0;
    sh[threadIdx.x] = v;
    __syncthreads();
    for (int off = 1; off < 1024; off <<= 1) {
        int t = (threadIdx.x >= off) ? sh[threadIdx.x - off] : 0;
        __syncthreads();
        sh[threadIdx.x] += t;
        __syncthreads();
    }
    if (i < n) g_offp[i] = sh[threadIdx.x] - v;
    if (threadIdx.x == 1023) g_bsum[blockIdx.x] = sh[1023];
}

__global__ void scan2_kernel(int nb) {
    __shared__ int sh[NB_MAX];
    int t = threadIdx.x;
    int v = (t < nb) ? g_bsum[t] : 0;
    sh[t] = v;
    __syncthreads();
    for (int off = 1; off < NB_MAX; off <<= 1) {
        int u = (t >= off) ? sh[t - off] : 0;
        __syncthreads();
        sh[t] += u;
        __syncthreads();
    }
    if (t < nb) g_bpre[t] = sh[t] - v;
}

// ---------------------------------------------------------------------------
// scatter: score + exp + countdown placement.
// count for node = cnt + 1 (self loop); slots [base, base+cnt]:
// old = atomicAdd(cnt, -1) in {cnt..cnt-count+1}; pos = base + old (self loop
// occupies old = 0 slot offset via +cnt ... all offsets 0..cnt covered once).
// g_cnt ends at -1... careful: decremented count = cnt+1 times -> ends at -1!
// Fix: self-loop items do NOT decrement; they take slot base + cnt directly
// is wrong (edge may also land there). Instead: edges decrement (cnt -> 0 after
// cnt edge-decrements), edge pos = base + old - 1 in [base, base+cnt-1]; the
// self-loop takes fixed slot base + cnt (the last one). cnt ends at 0. OK.
// ---------------------------------------------------------------------------
__global__ void scatter_kernel(const int* __restrict__ ei,
                               const float* __restrict__ batt, int E, int n) {
    int t = blockIdx.x * blockDim.x + threadIdx.x;
    if (t >= E + n) return;
    int src, dst, pos;
    if (t < E) {
        src = ei[t]; dst = ei[E + t];
        int old = atomicAdd(&g_cnt[src], -1);
        pos = g_offp[src] + g_bpre[src >> 10] + old - 1;
    } else {
        src = t - E; dst = src;
        int cnt = g_cnt[src];   // racy read is fine? NO - see below: use offp diff
        // self-loop slot = last slot of segment = next segment base - 1
        // compute from prefix sums (stable, race-free):
        pos = g_offp[src] + g_bpre[src >> 10];   // base
        // count = (next base) - base; need next base:
        // store at base + count - 1 == next_base - 1
        // next base computed via scan arrays of src+1 handled in host? We know
        // total layout: base of src+1 = offp[src+1]+bpre[(src+1)>>10] except src=n-1.
        (void)cnt;
    }
    float sc = g_si[src] + g_sj[dst] + batt[0];
    sc = (sc >= 0.f) ? sc : 0.01f * sc;
    float e = expf(sc);
    if (t >= E) {
        int nb_next = (t - E + 1 < n)
            ? (g_offp[t - E + 1] + g_bpre[(t - E + 1) >> 10])
            : (E + n);
        pos = nb_next - 1;
    }
    g_de[pos] = make_uint2((unsigned)dst, __float_as_uint(e));
}

// ---------------------------------------------------------------------------
// aggregation: warp per src node, fp16 gather, fp32 accumulate,
// fused normalize + ELU, coalesced write.
// ---------------------------------------------------------------------------
__global__ __launch_bounds__(256)
void aggregate_kernel(float* __restrict__ out, int n, int total) {
    int w = (blockIdx.x * blockDim.x + threadIdx.x) >> 5;
    int lane = threadIdx.x & 31;
    if (w >= n) return;
    int s = g_offp[w] + g_bpre[w >> 10];
    int e = (w + 1 < n) ? (g_offp[w + 1] + g_bpre[(w + 1) >> 10]) : total;

    float4 acc = make_float4(0.f, 0.f, 0.f, 0.f);
    float den = 0.f;

    int k = s;
    for (; k + 3 < e; k += 4) {
        uint2 de0 = g_de[k],     de1 = g_de[k + 1];
        uint2 de2 = g_de[k + 2], de3 = g_de[k + 3];
        uint2 r0 = *(const uint2*)&g_hh[(size_t)de0.x * D + lane * 4];
        uint2 r1 = *(const uint2*)&g_hh[(size_t)de1.x * D + lane * 4];
        uint2 r2 = *(const uint2*)&g_hh[(size_t)de2.x * D + lane * 4];
        uint2 r3 = *(const uint2*)&g_hh[(size_t)de3.x * D + lane * 4];
        float e0 = __uint_as_float(de0.y), e1 = __uint_as_float(de1.y);
        float e2 = __uint_as_float(de2.y), e3 = __uint_as_float(de3.y);
        float2 a0 = __half22float2(u32_to_h2(r0.x));
        float2 a1 = __half22float2(u32_to_h2(r0.y));
        acc.x += e0 * a0.x; acc.y += e0 * a0.y; acc.z += e0 * a1.x; acc.w += e0 * a1.y;
        a0 = __half22float2(u32_to_h2(r1.x));
        a1 = __half22float2(u32_to_h2(r1.y));
        acc.x += e1 * a0.x; acc.y += e1 * a0.y; acc.z += e1 * a1.x; acc.w += e1 * a1.y;
        a0 = __half22float2(u32_to_h2(r2.x));
        a1 = __half22float2(u32_to_h2(r2.y));
        acc.x += e2 * a0.x; acc.y += e2 * a0.y; acc.z += e2 * a1.x; acc.w += e2 * a1.y;
        a0 = __half22float2(u32_to_h2(r3.x));
        a1 = __half22float2(u32_to_h2(r3.y));
        acc.x += e3 * a0.x; acc.y += e3 * a0.y; acc.z += e3 * a1.x; acc.w += e3 * a1.y;
        den += (e0 + e1) + (e2 + e3);
    }
    for (; k < e; k++) {
        uint2 de0 = g_de[k];
        uint2 r0 = *(const uint2*)&g_hh[(size_t)de0.x * D + lane * 4];
        float e0 = __uint_as_float(de0.y);
        float2 a0 = __half22float2(u32_to_h2(r0.x));
        float2 a1 = __half22float2(u32_to_h2(r0.y));
        acc.x += e0 * a0.x; acc.y += e0 * a0.y; acc.z += e0 * a1.x; acc.w += e0 * a1.y;
        den += e0;
    }

    float inv = 1.f / den;
    float4 o;
    o.x = acc.x * inv; o.y = acc.y * inv; o.z = acc.z * inv; o.w = acc.w * inv;
    o.x = (o.x > 0.f) ? o.x : expm1f(o.x);
    o.y = (o.y > 0.f) ? o.y : expm1f(o.y);
    o.z = (o.z > 0.f) ? o.z : expm1f(o.z);
    o.w = (o.w > 0.f) ? o.w : expm1f(o.w);
    *(float4*)&out[(size_t)w * D + lane * 4] = o;
}

// ---------------------------------------------------------------------------
extern "C" void kernel_launch(void* const* d_in, const int* in_sizes, int n_in,
                              void* d_out, int out_size) {
    const float* x    = (const float*)d_in[0];
    const int*   ei   = (const int*)  d_in[1];
    const float* W    = (const float*)d_in[2];
    const float* b    = (const float*)d_in[3];
    const float* Watt = (const float*)d_in[4];
    const float* batt = (const float*)d_in[5];
    float* out = (float*)d_out;

    int n = in_sizes[0] / D;
    int E = in_sizes[1] / 2;
    int total = E + n;
    int nb = (n + 1023) / 1024;

    // side stream + events for fork/join inside graph capture (created once)
    static cudaStream_t s1 = nullptr;
    static cudaEvent_t ev_fork = nullptr, ev_join = nullptr;
    if (s1 == nullptr) {
        cudaStreamCreateWithFlags(&s1, cudaStreamNonBlocking);
        cudaEventCreateWithFlags(&ev_fork, cudaEventDisableTiming);
        cudaEventCreateWithFlags(&ev_join, cudaEventDisableTiming);
    }

    // fork: edge pipeline (hist -> scans) runs concurrent with GEMM
    cudaEventRecord(ev_fork, 0);
    cudaStreamWaitEvent(s1, ev_fork, 0);
    hist_kernel<<<(E + 255) / 256, 256, 0, s1>>>(ei, E);
    scan1_kernel<<<nb, 1024, 0, s1>>>(n);
    scan2_kernel<<<1, NB_MAX, 0, s1>>>(nb);
    cudaEventRecord(ev_join, s1);

    gemm_kernel<<<(n + 127) / 128, 256>>>(x, W, b, Watt, n);

    cudaStreamWaitEvent(0, ev_join, 0);
    scatter_kernel<<<(total + 255) / 256, 256>>>(ei, batt, E, n);
    aggregate_kernel<<<((long long)n * 32 + 255) / 256, 256>>>(out, n, total);
}